// round 2
// baseline (speedup 1.0000x reference)
#include <cuda_runtime.h>

// Problem constants (fixed by the dataset)
#define S_ 16384
#define N_ 2048
#define C_ 8
#define PAD 64                      // zero padding each side; |floor(shift)| << 64
#define ROW (N_ + 2 * PAD)          // 2176 floats per component row in smem
#define SMEM_BYTES (C_ * ROW * 4)   // 69632 B

#define NTHREADS 256
#define NBLOCKS 296                 // 2 CTAs/SM * 148 SMs
#define WARPS_PER_CTA (NTHREADS / 32)
#define NWARPS (NBLOCKS * WARPS_PER_CTA)   // 2368

#define GROUPS (S_ / 32)            // 512 sample-groups of 32 (one per lane)
#define CHUNK_COLS 64               // columns per task
#define CHUNKS (N_ / CHUNK_COLS)    // 32
#define NTASKS (GROUPS * CHUNKS)    // 16384

extern __shared__ float smem[];

__global__ __launch_bounds__(NTHREADS, 2)
void smf_shift_kernel(const float* __restrict__ components,
                      const float* __restrict__ contributions,
                      const float* __restrict__ shift,
                      float* __restrict__ out)
{
    // ---- Stage components into zero-padded shared memory ----
    for (int i = threadIdx.x; i < C_ * ROW; i += NTHREADS) smem[i] = 0.0f;
    __syncthreads();
    for (int i = threadIdx.x; i < C_ * N_; i += NTHREADS) {
        int c = i >> 11;          // / N_
        int j = i & (N_ - 1);     // % N_
        smem[c * ROW + PAD + j] = components[i];
    }
    __syncthreads();

    const int lane = threadIdx.x & 31;
    const int wid  = threadIdx.x >> 5;
    const int wg   = blockIdx.x * WARPS_PER_CTA + wid;

    for (int task = wg; task < NTASKS; task += NWARPS) {
        const int group = task >> 5;          // / CHUNKS
        const int chunk = task & (CHUNKS - 1);
        const int s  = group * 32 + lane;     // lane <-> sample
        const int n0 = chunk * CHUNK_COLS;

        // ---- Per-(s,c) parameters: d (integer shift), w0, w1 ----
        const float4* shp = reinterpret_cast<const float4*>(shift + (size_t)s * C_);
        const float4* ctp = reinterpret_cast<const float4*>(contributions + (size_t)s * C_);
        float4 sh0 = __ldg(shp), sh1 = __ldg(shp + 1);
        float4 ct0 = __ldg(ctp), ct1 = __ldg(ctp + 1);
        float shv[8] = {sh0.x, sh0.y, sh0.z, sh0.w, sh1.x, sh1.y, sh1.z, sh1.w};
        float ctv[8] = {ct0.x, ct0.y, ct0.z, ct0.w, ct1.x, ct1.y, ct1.z, ct1.w};

        float w0[8], w1[8], g[8];
        int idx[8];
        #pragma unroll
        for (int c = 0; c < 8; c++) {
            float sv = shv[c];
            float fl = floorf(sv);
            float f  = sv - fl;
            int d = (int)fl;
            d = max(-PAD, min(PAD - 1, d));   // memory-safety clamp (never hit by data)
            w0[c] = ctv[c] * (1.0f - f);
            w1[c] = ctv[c] * f;
            idx[c] = c * ROW + PAD + d + n0;
            g[c] = smem[idx[c]];              // carry register: comp[n + d]
        }

        float* optr = out + (size_t)s * N_ + n0;

        #pragma unroll 1
        for (int k8 = 0; k8 < CHUNK_COLS; k8 += 8) {
            float acc[8];
            #pragma unroll
            for (int k = 0; k < 8; k++) {
                float a = 0.0f;
                #pragma unroll
                for (int c = 0; c < 8; c++) {
                    // one LDS per (c,n): g1(n) == g0(n+1) carry trick
                    float gn = smem[idx[c] + k + 1];
                    a = fmaf(w0[c], g[c], a);
                    a = fmaf(w1[c], gn, a);
                    g[c] = gn;
                }
                acc[k] = a;
            }
            #pragma unroll
            for (int c = 0; c < 8; c++) idx[c] += 8;

            // 32B contiguous per lane -> full-sector writes
            float4* o = reinterpret_cast<float4*>(optr + k8);
            o[0] = make_float4(acc[0], acc[1], acc[2], acc[3]);
            o[1] = make_float4(acc[4], acc[5], acc[6], acc[7]);
        }
    }
}

extern "C" void kernel_launch(void* const* d_in, const int* in_sizes, int n_in,
                              void* d_out, int out_size)
{
    // metadata order: inputs (unused), components, contributions, shift
    const float* components    = (const float*)d_in[1];
    const float* contributions = (const float*)d_in[2];
    const float* shift         = (const float*)d_in[3];
    float* out = (float*)d_out;

    // 68KB dynamic smem > 48KB default: raise the limit (idempotent, not a stream op)
    cudaFuncSetAttribute(smf_shift_kernel,
                         cudaFuncAttributeMaxDynamicSharedMemorySize, SMEM_BYTES);

    smf_shift_kernel<<<NBLOCKS, NTHREADS, SMEM_BYTES>>>(
        components, contributions, shift, out);
}

// round 3
// speedup vs baseline: 1.0425x; 1.0425x over previous
#include <cuda_runtime.h>

// Problem constants (fixed by the dataset)
#define S_ 16384
#define N_ 2048
#define C_ 8
#define PAD 32                      // zero padding each side; |floor(shift)| <= ~15 for 3*N(0,1)
#define ROW (N_ + 2 * PAD)          // 2112 floats per component row in smem
#define SMEM_BYTES (C_ * ROW * 4)   // 67584 B

#define NTHREADS 512
#define NBLOCKS 296                 // 2 CTAs/SM * 148 SMs
#define WARPS_PER_CTA (NTHREADS / 32)
#define NWARPS (NBLOCKS * WARPS_PER_CTA)   // 4736

#define GROUPS (S_ / 32)            // 512 sample-groups of 32 (one per lane)
#define CHUNK_COLS 32               // columns per task
#define CHUNKS (N_ / CHUNK_COLS)    // 64
#define NTASKS (GROUPS * CHUNKS)    // 32768 -> 6.92 tasks/warp, 1.2% tail

extern __shared__ float smem[];

__global__ __launch_bounds__(NTHREADS, 2)
void smf_shift_kernel(const float* __restrict__ components,
                      const float* __restrict__ contributions,
                      const float* __restrict__ shift,
                      float* __restrict__ out)
{
    // ---- Stage components into zero-padded shared memory ----
    // Zero only the pad regions (left+right 32 floats per row)
    for (int i = threadIdx.x; i < C_ * PAD * 2; i += NTHREADS) {
        int c = i / (PAD * 2);
        int p = i % (PAD * 2);
        int off = (p < PAD) ? p : (ROW - PAD * 2 + p);
        smem[c * ROW + off] = 0.0f;
    }
    // float4 staging of the 8x2048 component matrix
    {
        const float4* src = reinterpret_cast<const float4*>(components);
        for (int i = threadIdx.x; i < C_ * N_ / 4; i += NTHREADS) {
            int c = i >> 9;           // / (N_/4)
            int j = i & (N_ / 4 - 1);
            float4 v = __ldg(src + i);
            *reinterpret_cast<float4*>(&smem[c * ROW + PAD + j * 4]) = v;
        }
    }
    __syncthreads();

    const int lane = threadIdx.x & 31;
    const int wid  = threadIdx.x >> 5;
    const int wg   = blockIdx.x * WARPS_PER_CTA + wid;

    for (int task = wg; task < NTASKS; task += NWARPS) {
        const int group = task >> 6;           // / CHUNKS
        const int chunk = task & (CHUNKS - 1);
        const int s  = group * 32 + lane;      // lane <-> sample
        const int n0 = chunk * CHUNK_COLS;

        // ---- Per-(s,c) parameters: d (integer shift), w0, w1 ----
        const float4* shp = reinterpret_cast<const float4*>(shift + (size_t)s * C_);
        const float4* ctp = reinterpret_cast<const float4*>(contributions + (size_t)s * C_);
        float4 sh0 = __ldg(shp), sh1 = __ldg(shp + 1);
        float4 ct0 = __ldg(ctp), ct1 = __ldg(ctp + 1);
        float shv[8] = {sh0.x, sh0.y, sh0.z, sh0.w, sh1.x, sh1.y, sh1.z, sh1.w};
        float ctv[8] = {ct0.x, ct0.y, ct0.z, ct0.w, ct1.x, ct1.y, ct1.z, ct1.w};

        float w0[8], w1[8], g[8];
        int idx[8];
        #pragma unroll
        for (int c = 0; c < 8; c++) {
            float sv = shv[c];
            float fl = floorf(sv);
            float f  = sv - fl;
            int d = (int)fl;
            d = max(-PAD, min(PAD - 1, d));    // memory-safety clamp (never hit by data)
            w0[c] = ctv[c] * (1.0f - f);
            w1[c] = ctv[c] * f;
            idx[c] = c * ROW + PAD + d + n0;
            g[c] = smem[idx[c]];               // carry register: comp[n + d]
        }

        float* optr = out + (size_t)s * N_ + n0;

        #pragma unroll 1
        for (int k8 = 0; k8 < CHUNK_COLS; k8 += 8) {
            float acc[8];
            #pragma unroll
            for (int k = 0; k < 8; k++) {
                float a = 0.0f;
                #pragma unroll
                for (int c = 0; c < 8; c++) {
                    // one LDS per (c,n): g1(n) == g0(n+1) carry trick
                    float gn = smem[idx[c] + k + 1];
                    a = fmaf(w0[c], g[c], a);
                    a = fmaf(w1[c], gn, a);
                    g[c] = gn;
                }
                acc[k] = a;
            }
            #pragma unroll
            for (int c = 0; c < 8; c++) idx[c] += 8;

            // 32B contiguous per lane -> full-sector writes
            float4* o = reinterpret_cast<float4*>(optr + k8);
            o[0] = make_float4(acc[0], acc[1], acc[2], acc[3]);
            o[1] = make_float4(acc[4], acc[5], acc[6], acc[7]);
        }
    }
}

extern "C" void kernel_launch(void* const* d_in, const int* in_sizes, int n_in,
                              void* d_out, int out_size)
{
    // metadata order: inputs (unused), components, contributions, shift
    const float* components    = (const float*)d_in[1];
    const float* contributions = (const float*)d_in[2];
    const float* shift         = (const float*)d_in[3];
    float* out = (float*)d_out;

    cudaFuncSetAttribute(smf_shift_kernel,
                         cudaFuncAttributeMaxDynamicSharedMemorySize, SMEM_BYTES);

    smf_shift_kernel<<<NBLOCKS, NTHREADS, SMEM_BYTES>>>(
        components, contributions, shift, out);
}